// round 7
// baseline (speedup 1.0000x reference)
#include <cuda_runtime.h>
#include <cstdint>

#define Nn   2048
#define Ee   65536
#define INC  128
#define HIDc 32
#define LATc 16
#define NB   148
#define NT   256
#define TT   (NB*NT)

typedef unsigned long long ull;

// ---------------- scratch (static zero; self-cleaning each run) ----------------
__device__ float g_deg [Nn];                      // edge count only; consumer adds self-loop, resets to 0
__device__ float g_dinv[Nn];
__device__ __align__(16) float g_xw   [Nn*HIDc];
__device__ __align__(16) float g_agg1 [Nn*HIDc]; // reset by consumer (h1hw)
__device__ __align__(16) float g_hwmu [Nn*LATc];
__device__ __align__(16) float g_hwlv [Nn*LATc];
__device__ __align__(16) float g_aggmu[Nn*LATc]; // reset by consumer (zhij)
__device__ __align__(16) float g_agglv[Nn*LATc]; // reset by consumer (zhij)
__device__ __align__(16) float g_hi   [Nn*LATc];
__device__ __align__(16) float g_hjT  [LATc*Nn];

__device__ unsigned          g_bar_arr[8];        // self-resetting
__device__ volatile unsigned g_bar_rel[8];        // monotonic

// ---------------- helpers ----------------
__device__ __forceinline__ int eidx(const void* p, int pos, int is64) {
    if (is64) return (int)((const long long*)p)[pos];
    return ((const int*)p)[pos];
}
__device__ __forceinline__ void red4(float* addr, float4 v) {
    asm volatile("red.global.add.v4.f32 [%0], {%1, %2, %3, %4};"
                 :: "l"(__cvta_generic_to_global(addr)),
                    "f"(v.x), "f"(v.y), "f"(v.z), "f"(v.w) : "memory");
}
__device__ __forceinline__ ull f32x2_add(ull a, ull b) {
    ull r; asm("add.rn.f32x2 %0, %1, %2;" : "=l"(r) : "l"(a), "l"(b)); return r;
}
__device__ __forceinline__ ull f32x2_fma(ull a, ull b, ull c) {
    ull r; asm("fma.rn.f32x2 %0, %1, %2, %3;" : "=l"(r) : "l"(a), "l"(b), "l"(c)); return r;
}
__device__ __forceinline__ ull pack2(float lo, float hi) {
    ull r; asm("mov.b64 %0, {%1, %2};" : "=l"(r) : "f"(lo), "f"(hi)); return r;
}
__device__ __forceinline__ float2 unpack2(ull v) {
    float2 f; asm("mov.b64 {%0, %1}, %2;" : "=f"(f.x), "=f"(f.y) : "l"(v)); return f;
}
__device__ __forceinline__ ull relu2(ull v) {
    float2 f = unpack2(v);
    return pack2(fmaxf(f.x, 0.f), fmaxf(f.y, 0.f));
}

// grid barrier: all NB blocks resident by construction (launch_bounds(256,2))
__device__ __forceinline__ void gbar(int b) {
    __syncthreads();
    if (threadIdx.x == 0) {
        unsigned before = g_bar_rel[b];
        __threadfence();                            // cumulative: publishes block's prior writes
        if (atomicAdd(&g_bar_arr[b], 1u) == NB - 1) {
            g_bar_arr[b] = 0;                       // self-reset for next replay
            __threadfence();
            atomicAdd((unsigned*)&g_bar_rel[b], 1u);
        } else {
            while (g_bar_rel[b] == before) __nanosleep(32);
            __threadfence();                        // acquire
        }
    }
    __syncthreads();
}

// ---------------- the one kernel ----------------
__global__ void __launch_bounds__(NT, 2)
k_all(const float* __restrict__ x,   const float* __restrict__ eps,
      const float* __restrict__ W1,  const float* __restrict__ b1,
      const float* __restrict__ Wmu, const float* __restrict__ bmu,
      const float* __restrict__ Wlv, const float* __restrict__ blv,
      const float* __restrict__ dW1, const float* __restrict__ db1,
      const float* __restrict__ dW2, const float* __restrict__ db2,
      const void*  __restrict__ ei,  const void*  __restrict__ eit,
      float* __restrict__ adj, float* __restrict__ adjt,
      float* __restrict__ out_mu, float* __restrict__ out_lv)
{
    __shared__ int   s_is64;
    __shared__ float his[8][16];

    const int tx   = threadIdx.x;
    const int gtid = blockIdx.x * NT + tx;
    const int warp = blockIdx.x * (NT/32) + (tx >> 5);   // 0..1183
    const int lane = tx & 31;

    // ---- per-block dtype detection (512B, L2-broadcast) ----
    if (tx == 0) {
        const ull* p = (const ull*)ei;
        ull orv = 0;
#pragma unroll
        for (int k = 0; k < 64; k++) orv |= p[k];
        s_is64 = ((orv >> 32) == 0ull) ? 1 : 0;
    }
    __syncthreads();
    const int is64 = s_is64;

    // ================= P0: deg atomics + zero adj_true =================
    for (int e = gtid; e < Ee; e += TT)
        atomicAdd(&g_deg[eidx(ei, Ee + e, is64)], 1.0f);
    {
        float4* a4 = (float4*)adjt;
        for (int t = gtid; t < Nn * Nn / 4; t += TT)
            a4[t] = make_float4(0.f, 0.f, 0.f, 0.f);
    }
    gbar(0);

    // ========== P1: dinv (+deg reset) | xw = x@W1 | adj_true scatter ==========
    if (gtid < Nn) {
        g_dinv[gtid] = rsqrtf(g_deg[gtid] + 1.0f);   // +1 = self-loop
        g_deg[gtid]  = 0.f;                          // reset for next replay
    }
    for (int row = warp; row < Nn; row += NB * (NT/32)) {
        float xr[4];
#pragma unroll
        for (int k0 = 0; k0 < 4; k0++) xr[k0] = x[row * INC + k0 * 32 + lane];
        float s = 0.f;
#pragma unroll
        for (int k0 = 0; k0 < 4; k0++)
#pragma unroll
            for (int kk = 0; kk < 32; kk++) {
                float xv = __shfl_sync(0xffffffffu, xr[k0], kk);
                s = fmaf(xv, W1[(k0 * 32 + kk) * HIDc + lane], s);
            }
        g_xw[row * HIDc + lane] = s;
    }
    for (int e = gtid; e < Ee; e += TT)
        atomicAdd(&adjt[eidx(eit, e, is64) * Nn + eidx(eit, Ee + e, is64)], 1.0f);
    gbar(1);

    // ================= P2: edge aggregation layer 1 (red.v4) =================
    for (int t = gtid; t < Ee * 4; t += TT) {
        int e = t >> 2, c = t & 3;
        int s = eidx(ei, e, is64), d = eidx(ei, Ee + e, is64);
        float nw = g_dinv[s] * g_dinv[d];
        const float4* xw4 = (const float4*)g_xw;
        float4 a = xw4[s * 8 + c];
        float4 b = xw4[s * 8 + c + 4];
        a.x *= nw; a.y *= nw; a.z *= nw; a.w *= nw;
        b.x *= nw; b.y *= nw; b.z *= nw; b.w *= nw;
        red4(&g_agg1[d * HIDc + c * 4], a);
        red4(&g_agg1[d * HIDc + (c + 4) * 4], b);
    }
    gbar(2);

    // ===== P3: h1 = relu(agg + selfloop + b1); hw = h1@{Wmu,Wlv}; reset agg1 =====
    for (int row = warp; row < Nn; row += NB * (NT/32)) {
        float di = g_dinv[row];
        int idx = row * HIDc + lane;
        float h = fmaxf(g_agg1[idx] + di * di * g_xw[idx] + b1[lane], 0.f);
        g_agg1[idx] = 0.f;                           // reset for next replay
        const float* W = (lane < 16) ? Wmu : Wlv;
        int l = lane & 15;
        float s = 0.f;
#pragma unroll
        for (int k = 0; k < HIDc; k++) {
            float hk = __shfl_sync(0xffffffffu, h, k);
            s = fmaf(hk, W[k * LATc + l], s);
        }
        if (lane < 16) g_hwmu[row * LATc + l] = s;
        else           g_hwlv[row * LATc + l] = s;
    }
    gbar(3);

    // ================= P4: edge aggregation layer 2 (red.v4) =================
    for (int t = gtid; t < Ee * 4; t += TT) {
        int e = t >> 2, c = t & 3;
        int s = eidx(ei, e, is64), d = eidx(ei, Ee + e, is64);
        float nw = g_dinv[s] * g_dinv[d];
        float4 a = ((const float4*)g_hwmu)[s * 4 + c];
        float4 b = ((const float4*)g_hwlv)[s * 4 + c];
        a.x *= nw; a.y *= nw; a.z *= nw; a.w *= nw;
        b.x *= nw; b.y *= nw; b.z *= nw; b.w *= nw;
        red4(&g_aggmu[d * LATc + c * 4], a);
        red4(&g_agglv[d * LATc + c * 4], b);
    }
    gbar(4);

    // ===== P5: mu/logvar out, z (regs), hi/hjT via shfl-16; reset aggmu/lv =====
    if (gtid < Nn * LATc) {                          // whole warps in/out (32768 % 32 == 0)
        int t = gtid, i = t >> 4, l = t & 15;
        float di = g_dinv[i]; float d2 = di * di;
        float mu = g_aggmu[t] + d2 * g_hwmu[t] + bmu[l];
        float lv = g_agglv[t] + d2 * g_hwlv[t] + blv[l];
        g_aggmu[t] = 0.f; g_agglv[t] = 0.f;          // reset for next replay
        out_mu[t] = mu;
        out_lv[t] = lv;
        float z = fmaf(eps[t], __expf(0.5f * lv), mu);
        float si = db1[l], sj = 0.f;
#pragma unroll
        for (int k = 0; k < LATc; k++) {
            float zk = __shfl_sync(0xffffffffu, z, k, 16);
            si = fmaf(zk, dW1[k * LATc + l], si);
            sj = fmaf(zk, dW1[(LATc + k) * LATc + l], sj);
        }
        g_hi[t] = si;
        g_hjT[l * Nn + i] = sj;
    }
    gbar(5);

    // ================= P6: decoder, tiles of 8 rows x 512 cols =================
    {
        ull w2p[LATc];
        float b2 = db2[0];
#pragma unroll
        for (int l = 0; l < LATc; l++) { float w = dW2[l]; w2p[l] = pack2(w, w); }

        for (int tt = blockIdx.x; tt < 1024; tt += NB) {   // 4 x 256 tiles
            int it = tt & 255, jt = tt >> 8;
            int i0 = it * 8, j0 = jt * 512;
            __syncthreads();                          // protect his reuse across tiles
            if (tx < 128) his[tx >> 4][tx & 15] = g_hi[(i0 + (tx >> 4)) * LATc + (tx & 15)];
            ull pj[LATc];
#pragma unroll
            for (int l = 0; l < LATc; l++) {
                float2 h = *(const float2*)&g_hjT[l * Nn + j0 + 2 * tx];
                pj[l] = pack2(h.x, h.y);
            }
            __syncthreads();
            size_t obase = (size_t)i0 * Nn + j0 + 2 * tx;
#pragma unroll
            for (int r = 0; r < 8; r++) {
                ull acc = pack2(b2, b2);
#pragma unroll
                for (int l = 0; l < LATc; l++) {
                    float h = his[r][l];
                    acc = f32x2_fma(relu2(f32x2_add(pj[l], pack2(h, h))), w2p[l], acc);
                }
                float2 s = unpack2(acc);
                float2 o;
                o.x = __fdividef(1.f, 1.f + __expf(-s.x));
                o.y = __fdividef(1.f, 1.f + __expf(-s.y));
                *(float2*)&adj[obase + (size_t)r * Nn] = o;
            }
        }
    }
}

// ---------------- launcher ----------------
extern "C" void kernel_launch(void* const* d_in, const int* in_sizes, int n_in,
                              void* d_out, int out_size) {
    const float* x    = (const float*)d_in[0];
    const float* eps  = (const float*)d_in[1];
    const float* W1   = (const float*)d_in[2];
    const float* b1   = (const float*)d_in[3];
    const float* Wmu  = (const float*)d_in[4];
    const float* bmu  = (const float*)d_in[5];
    const float* Wlv  = (const float*)d_in[6];
    const float* blv  = (const float*)d_in[7];
    const float* dW1  = (const float*)d_in[8];
    const float* db1  = (const float*)d_in[9];
    const float* dW2  = (const float*)d_in[10];
    const float* db2  = (const float*)d_in[11];
    const void*  ei   = d_in[12];
    const void*  eit  = d_in[13];

    float* out      = (float*)d_out;
    float* adj_pred = out;
    float* adj_true = out + (size_t)Nn * Nn;
    float* out_mu   = out + 2 * (size_t)Nn * Nn;
    float* out_lv   = out_mu + Nn * LATc;

    k_all<<<NB, NT>>>(x, eps, W1, b1, Wmu, bmu, Wlv, blv, dW1, db1, dW2, db2,
                      ei, eit, adj_pred, adj_true, out_mu, out_lv);
}

// round 8
// speedup vs baseline: 1.3145x; 1.3145x over previous
#include <cuda_runtime.h>
#include <cstdint>

#define Nn   2048
#define Ee   65536
#define INC  128
#define HIDc 32
#define LATc 16

typedef unsigned long long ull;

// ---------------- scratch (static zero; self-cleaning each run) ----------------
__device__ int   g_is64;
__device__ float g_deg [Nn];                       // edge count only; reset by k_xw_dinv_true
__device__ float g_dinv[Nn];
__device__ __align__(16) float g_xw   [Nn*HIDc];
__device__ __align__(16) float g_agg1 [Nn*HIDc];  // reset by k_h1hw
__device__ __align__(16) float g_hwmu [Nn*LATc];
__device__ __align__(16) float g_hwlv [Nn*LATc];
__device__ __align__(16) float g_aggmu[Nn*LATc];  // reset by k_zhij
__device__ __align__(16) float g_agglv[Nn*LATc];  // reset by k_zhij
__device__ __align__(16) float g_hi   [Nn*LATc];
__device__ __align__(16) float g_hjT  [LATc*Nn];  // transposed: [l][i]

// ---------------- helpers ----------------
__device__ __forceinline__ int eidx(const void* p, int pos, int is64) {
    if (is64) return (int)((const long long*)p)[pos];
    return ((const int*)p)[pos];
}
__device__ __forceinline__ void red4(float* addr, float4 v) {
    asm volatile("red.global.add.v4.f32 [%0], {%1, %2, %3, %4};"
                 :: "l"(__cvta_generic_to_global(addr)),
                    "f"(v.x), "f"(v.y), "f"(v.z), "f"(v.w) : "memory");
}
__device__ __forceinline__ ull f32x2_add(ull a, ull b) {
    ull r; asm("add.rn.f32x2 %0, %1, %2;" : "=l"(r) : "l"(a), "l"(b)); return r;
}
__device__ __forceinline__ ull f32x2_fma(ull a, ull b, ull c) {
    ull r; asm("fma.rn.f32x2 %0, %1, %2, %3;" : "=l"(r) : "l"(a), "l"(b), "l"(c)); return r;
}
__device__ __forceinline__ ull pack2(float lo, float hi) {
    ull r; asm("mov.b64 %0, {%1, %2};" : "=l"(r) : "f"(lo), "f"(hi)); return r;
}
__device__ __forceinline__ float2 unpack2(ull v) {
    float2 f; asm("mov.b64 {%0, %1}, %2;" : "=f"(f.x), "=f"(f.y) : "l"(v)); return f;
}
__device__ __forceinline__ ull relu2(ull v) {
    float2 f = unpack2(v);
    return pack2(fmaxf(f.x, 0.f), fmaxf(f.y, 0.f));
}

// ---------------- kernels ----------------

// L1: dtype detect (per block) + deg atomics + zero adj_true (overlapped)
__global__ void k_pre(const void* __restrict__ ei, float* __restrict__ adjt) {
    __shared__ int s_is64;
    int tx = threadIdx.x;
    if (tx == 0) {
        const ull* p = (const ull*)ei;
        ull orv = 0;
#pragma unroll
        for (int k = 0; k < 64; k++) orv |= p[k];
        s_is64 = ((orv >> 32) == 0ull) ? 1 : 0;
        if (blockIdx.x == 0) g_is64 = s_is64;        // publish for later launches
    }
    __syncthreads();
    int is64 = s_is64;
    int gtid = blockIdx.x * 256 + tx;                // 65536 threads
    atomicAdd(&g_deg[eidx(ei, Ee + gtid, is64)], 1.0f);
    float4* a4 = (float4*)adjt;
#pragma unroll
    for (int k = 0; k < 16; k++)                     // 1M float4s total
        a4[gtid + k * 65536] = make_float4(0.f, 0.f, 0.f, 0.f);
}

// L2: dinv (+deg reset) | xw = x @ W1 (warp/row) | adj_true scatter
__global__ void k_xw_dinv_true(const float* __restrict__ x, const float* __restrict__ W1,
                               const void* __restrict__ eit) {
    __shared__ float xs[8][INC];
    int tid = threadIdx.y * 32 + threadIdx.x;
    if (blockIdx.x < 8) {
        int i = blockIdx.x * 256 + tid;
        g_dinv[i] = rsqrtf(g_deg[i] + 1.0f);         // +1 = self-loop
        g_deg[i]  = 0.f;                             // reset for next replay
    }
    for (int t = tid; t < 8 * INC; t += 256) {
        int r = t / INC, k = t % INC;
        xs[r][k] = x[(blockIdx.x * 8 + r) * INC + k];
    }
    __syncthreads();
    int row = blockIdx.x * 8 + threadIdx.y;
    int c   = threadIdx.x;
    float s = 0.f;
#pragma unroll 8
    for (int k = 0; k < INC; k++) s = fmaf(xs[threadIdx.y][k], W1[k * HIDc + c], s);
    g_xw[row * HIDc + c] = s;
    // adj_true scatter (zeroed in L1; stream order guarantees visibility)
    {
        int is64 = g_is64;
        int e = blockIdx.x * 256 + tid;              // 65536 = Ee exactly
        float* adjt = (float*)(( (char*)0 ) );       // placeholder avoided below
        (void)adjt;
        extern __device__ float* g_adjt_p;           // not used; see param version
    }
}

// real scatter lives here (needs adjt pointer): folded via separate small param kernel is
// avoided — scatter is issued from k_xw_dinv_true via this device pointer set each launch.
__device__ float* g_adjt;

__global__ void k_xw_dinv_true2(const float* __restrict__ x, const float* __restrict__ W1,
                                const void* __restrict__ eit, float* __restrict__ adjt) {
    __shared__ float xs[8][INC];
    int tid = threadIdx.y * 32 + threadIdx.x;
    if (blockIdx.x < 8) {
        int i = blockIdx.x * 256 + tid;
        g_dinv[i] = rsqrtf(g_deg[i] + 1.0f);         // +1 = self-loop
        g_deg[i]  = 0.f;                             // reset for next replay
    }
    // adj_true scatter first (independent of smem fill)
    {
        int is64 = g_is64;
        int e = blockIdx.x * 256 + tid;              // 65536 = Ee exactly
        atomicAdd(&adjt[eidx(eit, e, is64) * Nn + eidx(eit, Ee + e, is64)], 1.0f);
    }
    for (int t = tid; t < 8 * INC; t += 256) {
        int r = t / INC, k = t % INC;
        xs[r][k] = x[(blockIdx.x * 8 + r) * INC + k];
    }
    __syncthreads();
    int row = blockIdx.x * 8 + threadIdx.y;
    int c   = threadIdx.x;
    float s = 0.f;
#pragma unroll 8
    for (int k = 0; k < INC; k++) s = fmaf(xs[threadIdx.y][k], W1[k * HIDc + c], s);
    g_xw[row * HIDc + c] = s;
}

// L3: edge aggregation layer 1 — 4 edges per thread (MLP=4), red.v4
__global__ void k_eagg1(const void* __restrict__ ei) {
    int t = blockIdx.x * 256 + threadIdx.x;          // 65536 threads
    int c = t & 3, e0 = t >> 2;                      // e0 in 0..16383
    int is64 = g_is64;
    int s[4], d[4];
#pragma unroll
    for (int k = 0; k < 4; k++) {
        int e = e0 + k * 16384;
        s[k] = eidx(ei, e, is64);
        d[k] = eidx(ei, Ee + e, is64);
    }
    float nw[4];
#pragma unroll
    for (int k = 0; k < 4; k++) nw[k] = g_dinv[s[k]] * g_dinv[d[k]];
    const float4* xw4 = (const float4*)g_xw;
    float4 a[4], b[4];
#pragma unroll
    for (int k = 0; k < 4; k++) {
        a[k] = xw4[s[k] * 8 + c];
        b[k] = xw4[s[k] * 8 + c + 4];
    }
#pragma unroll
    for (int k = 0; k < 4; k++) {
        float w = nw[k];
        a[k].x *= w; a[k].y *= w; a[k].z *= w; a[k].w *= w;
        b[k].x *= w; b[k].y *= w; b[k].z *= w; b[k].w *= w;
        red4(&g_agg1[d[k] * HIDc + c * 4], a[k]);
        red4(&g_agg1[d[k] * HIDc + (c + 4) * 4], b[k]);
    }
}

// L4: h1 = relu(agg + selfloop + b1) fused with hw = h1 @ {W_mu, W_lv}; reset agg1
__global__ void k_h1hw(const float* __restrict__ b1,
                       const float* __restrict__ Wmu, const float* __restrict__ Wlv) {
    int row  = blockIdx.x * 8 + (threadIdx.x >> 5);
    int lane = threadIdx.x & 31;
    float di = g_dinv[row];
    int idx = row * HIDc + lane;
    float h = fmaxf(g_agg1[idx] + di * di * g_xw[idx] + b1[lane], 0.f);
    g_agg1[idx] = 0.f;                               // reset for next replay
    const float* W = (lane < 16) ? Wmu : Wlv;
    int l = lane & 15;
    float s = 0.f;
#pragma unroll
    for (int k = 0; k < HIDc; k++) {
        float hk = __shfl_sync(0xffffffffu, h, k);
        s = fmaf(hk, W[k * LATc + l], s);
    }
    if (lane < 16) g_hwmu[row * LATc + l] = s;
    else           g_hwlv[row * LATc + l] = s;
}

// L5: edge aggregation layer 2 — 4 edges per thread (MLP=4), red.v4
__global__ void k_eagg2(const void* __restrict__ ei) {
    int t = blockIdx.x * 256 + threadIdx.x;          // 65536 threads
    int c = t & 3, e0 = t >> 2;
    int is64 = g_is64;
    int s[4], d[4];
#pragma unroll
    for (int k = 0; k < 4; k++) {
        int e = e0 + k * 16384;
        s[k] = eidx(ei, e, is64);
        d[k] = eidx(ei, Ee + e, is64);
    }
    float nw[4];
#pragma unroll
    for (int k = 0; k < 4; k++) nw[k] = g_dinv[s[k]] * g_dinv[d[k]];
    float4 a[4], b[4];
#pragma unroll
    for (int k = 0; k < 4; k++) {
        a[k] = ((const float4*)g_hwmu)[s[k] * 4 + c];
        b[k] = ((const float4*)g_hwlv)[s[k] * 4 + c];
    }
#pragma unroll
    for (int k = 0; k < 4; k++) {
        float w = nw[k];
        a[k].x *= w; a[k].y *= w; a[k].z *= w; a[k].w *= w;
        b[k].x *= w; b[k].y *= w; b[k].z *= w; b[k].w *= w;
        red4(&g_aggmu[d[k] * LATc + c * 4], a[k]);
        red4(&g_agglv[d[k] * LATc + c * 4], b[k]);
    }
}

// L6: mu/logvar out, z (regs), hi/hjT via shfl-16 matvec; reset aggmu/agglv
__global__ void k_zhij(const float* __restrict__ bmu, const float* __restrict__ blv,
                       const float* __restrict__ eps,
                       const float* __restrict__ dW1, const float* __restrict__ db1,
                       float* __restrict__ out_mu, float* __restrict__ out_lv) {
    int t = blockIdx.x * 256 + threadIdx.x;          // Nn*LATc threads
    int i = t >> 4, l = t & 15;
    float di = g_dinv[i]; float d2 = di * di;
    float mu = g_aggmu[t] + d2 * g_hwmu[t] + bmu[l];
    float lv = g_agglv[t] + d2 * g_hwlv[t] + blv[l];
    g_aggmu[t] = 0.f; g_agglv[t] = 0.f;              // reset for next replay
    out_mu[t] = mu;
    out_lv[t] = lv;
    float z = fmaf(eps[t], __expf(0.5f * lv), mu);
    float si = db1[l], sj = 0.f;
#pragma unroll
    for (int k = 0; k < LATc; k++) {
        float zk = __shfl_sync(0xffffffffu, z, k, 16);
        si = fmaf(zk, dW1[k * LATc + l], si);
        sj = fmaf(zk, dW1[(LATc + k) * LATc + l], sj);
    }
    g_hi[t] = si;
    g_hjT[l * Nn + i] = sj;                          // transposed for k_dec
}

// L7: decoder. block = 128 thr, tile = 8 rows x 256 cols; packed f32x2 math
__global__ void __launch_bounds__(128) k_dec(const float* __restrict__ dW2,
                                             const float* __restrict__ db2,
                                             float* __restrict__ adj) {
    __shared__ float his[8][16];
    int tx = threadIdx.x;
    int j0 = blockIdx.x * 256;
    int i0 = blockIdx.y * 8;

    if (tx < 128) his[tx >> 4][tx & 15] = g_hi[(i0 + (tx >> 4)) * LATc + (tx & 15)];

    ull w2p[LATc], pj[LATc];
    float b2 = db2[0];
#pragma unroll
    for (int l = 0; l < LATc; l++) {
        float w = dW2[l];
        w2p[l] = pack2(w, w);
        float2 h = *(const float2*)&g_hjT[l * Nn + j0 + 2 * tx];
        pj[l] = pack2(h.x, h.y);
    }
    __syncthreads();

    size_t obase = (size_t)i0 * Nn + j0 + 2 * tx;
#pragma unroll
    for (int r = 0; r < 8; r++) {
        ull acc = pack2(b2, b2);
#pragma unroll
        for (int l = 0; l < LATc; l++) {
            float h = his[r][l];
            acc = f32x2_fma(relu2(f32x2_add(pj[l], pack2(h, h))), w2p[l], acc);
        }
        float2 s = unpack2(acc);
        float2 o;
        o.x = __fdividef(1.f, 1.f + __expf(-s.x));
        o.y = __fdividef(1.f, 1.f + __expf(-s.y));
        *(float2*)&adj[obase + (size_t)r * Nn] = o;
    }
}

// ---------------- launcher ----------------
extern "C" void kernel_launch(void* const* d_in, const int* in_sizes, int n_in,
                              void* d_out, int out_size) {
    const float* x    = (const float*)d_in[0];
    const float* eps  = (const float*)d_in[1];
    const float* W1   = (const float*)d_in[2];
    const float* b1   = (const float*)d_in[3];
    const float* Wmu  = (const float*)d_in[4];
    const float* bmu  = (const float*)d_in[5];
    const float* Wlv  = (const float*)d_in[6];
    const float* blv  = (const float*)d_in[7];
    const float* dW1  = (const float*)d_in[8];
    const float* db1  = (const float*)d_in[9];
    const float* dW2  = (const float*)d_in[10];
    const float* db2  = (const float*)d_in[11];
    const void*  ei   = d_in[12];
    const void*  eit  = d_in[13];

    float* out      = (float*)d_out;
    float* adj_pred = out;
    float* adj_true = out + (size_t)Nn * Nn;
    float* out_mu   = out + 2 * (size_t)Nn * Nn;
    float* out_lv   = out_mu + Nn * LATc;

    k_pre          <<<256, 256>>>(ei, adj_true);
    k_xw_dinv_true2<<<256, dim3(32, 8)>>>(x, W1, eit, adj_true);
    k_eagg1        <<<256, 256>>>(ei);
    k_h1hw         <<<256, 256>>>(b1, Wmu, Wlv);
    k_eagg2        <<<256, 256>>>(ei);
    k_zhij         <<<128, 256>>>(bmu, blv, eps, dW1, db1, out_mu, out_lv);
    k_dec          <<<dim3(8, 256), 128>>>(dW2, db2, adj_pred);
}